// round 6
// baseline (speedup 1.0000x reference)
#include <cuda_runtime.h>
#include <cuda_bf16.h>
#include <cstdint>
#include <math.h>

#define NQ     65536
#define DIMIN  1024
#define DIMH   256
#define NCLUS  8
#define BM     64
#define BN     256
#define BK     64
#define NBLK   (NQ / BM)       // 1024
#define NITER  (DIMIN / BK)    // 16

// smem layout (bytes)
#define LDA      144                 // 64 bf16 (128B) + 16B pad
#define STAGE_A  (64 * LDA)          // 9216
#define STAGE_B  (256 * LDA)         // 36864
#define STAGE    (STAGE_A + STAGE_B) // 46080
#define OFF_A(s) ((unsigned)(s) * STAGE)
#define OFF_B(s) ((unsigned)(s) * STAGE + STAGE_A)
#define HLD      260
#define OFF_EXTRA 138240u            // 3 stages; hbuf (64*260*4=66560) unioned
#define OFF_B1   OFF_EXTRA
#define OFF_CID  (OFF_B1 + 1024u)
#define OFF_CNT  (OFF_CID + 256u)
#define SMEM_DYN (OFF_CNT + 32u)     // ~139.6 KB -> 1 CTA/SM

// ---- device scratch ----
__device__ __nv_bfloat16 g_W1bf[DIMH * DIMIN];        // 512 KB
__device__ float g_scratch[NBLK * NCLUS * DIMH];      // 8 MB
__device__ int   g_scnt[NBLK * NCLUS];
__device__ float g_seg[NCLUS * DIMH];
__device__ int   g_cnt[NCLUS];
__device__ float g_hp[NCLUS * DIMH];
__device__ float g_Ag[NCLUS];

// ---- helpers ----
__device__ __forceinline__ uint32_t smem_u32(const void* p) {
    uint32_t a;
    asm("{ .reg .u64 t; cvta.to.shared.u64 t, %1; cvt.u32.u64 %0, t; }" : "=r"(a) : "l"(p));
    return a;
}

__device__ __forceinline__ void ldm4(uint32_t* r, uint32_t addr) {
    asm volatile("ldmatrix.sync.aligned.m8n8.x4.shared.b16 {%0,%1,%2,%3}, [%4];"
                 : "=r"(r[0]), "=r"(r[1]), "=r"(r[2]), "=r"(r[3]) : "r"(addr));
}

__device__ __forceinline__ void mma_bf16(float* d, const uint32_t* a,
                                         uint32_t b0, uint32_t b1) {
    asm volatile("mma.sync.aligned.m16n8k16.row.col.f32.bf16.bf16.f32 "
                 "{%0,%1,%2,%3}, {%4,%5,%6,%7}, {%8,%9}, {%0,%1,%2,%3};"
                 : "+f"(d[0]), "+f"(d[1]), "+f"(d[2]), "+f"(d[3])
                 : "r"(a[0]), "r"(a[1]), "r"(a[2]), "r"(a[3]), "r"(b0), "r"(b1));
}

// B tile: 256 rows x 64 bf16 = 2048 x 16B chunks, 8 per thread
__device__ __forceinline__ void cp_B(uint32_t base, int s, int k0, int tid) {
    uint32_t dst = base + OFF_B(s);
    const char* src = (const char*)g_W1bf + (size_t)k0 * 2;
    #pragma unroll
    for (int i = 0; i < 8; i++) {
        int c  = tid + 256 * i;
        int n  = c >> 3, kc = c & 7;
        uint32_t d = dst + (unsigned)n * LDA + (unsigned)kc * 16;
        const void* g = src + (size_t)n * (DIMIN * 2) + kc * 16;
        asm volatile("cp.async.cg.shared.global [%0], [%1], 16;" :: "r"(d), "l"(g));
    }
}

// A tile: 64 rows x 64 fp32 cols, 4 float4 per thread
__device__ __forceinline__ void ldgA(float4* areg, const float* x,
                                     int row0, int it, int tid) {
    const int r0 = tid >> 4, fc = tid & 15;
    const float* p = x + (size_t)(row0 + r0) * DIMIN + it * BK + fc * 4;
    #pragma unroll
    for (int i = 0; i < 4; i++)
        areg[i] = *(const float4*)(p + (size_t)(16 * i) * DIMIN);
}

__device__ __forceinline__ void stsA(uint32_t sA, const float4* areg, int tid) {
    const int r0 = tid >> 4, fc = tid & 15;
    #pragma unroll
    for (int i = 0; i < 4; i++) {
        __nv_bfloat162 lo = __floats2bfloat162_rn(areg[i].x, areg[i].y);
        __nv_bfloat162 hi = __floats2bfloat162_rn(areg[i].z, areg[i].w);
        uint32_t u0 = *(uint32_t*)&lo, u1 = *(uint32_t*)&hi;
        uint32_t d = sA + (unsigned)(r0 + 16 * i) * LDA + (unsigned)fc * 8;
        asm volatile("st.shared.v2.b32 [%0], {%1,%2};" :: "r"(d), "r"(u0), "r"(u1));
    }
}

// ---------------------------------------------------------------------------
// K0: W1 fp32 -> bf16
// ---------------------------------------------------------------------------
__global__ __launch_bounds__(256)
void k_w1cvt(const float* __restrict__ W1) {
    int i = (blockIdx.x * 256 + threadIdx.x) * 4;
    float4 v = *(const float4*)(W1 + i);
    __nv_bfloat162 lo = __floats2bfloat162_rn(v.x, v.y);
    __nv_bfloat162 hi = __floats2bfloat162_rn(v.z, v.w);
    uint2 u;
    u.x = *(uint32_t*)&lo;
    u.y = *(uint32_t*)&hi;
    *(uint2*)&g_W1bf[i] = u;
}

// ---------------------------------------------------------------------------
// K1: bf16 mma GEMM 64x256 per CTA, 256 thr (8 warps, warp tile 32x64),
//     3-stage cp.async pipeline, fused bias+relu+cluster sums
// ---------------------------------------------------------------------------
__global__ __launch_bounds__(256, 1)
void k_gemm_seg(const float* __restrict__ x, const int* __restrict__ cid,
                const float* __restrict__ b1)
{
    extern __shared__ char sm[];
    const uint32_t base = smem_u32(sm);
    float* b1s   = (float*)(sm + OFF_B1);
    int*   cid_s = (int*)  (sm + OFF_CID);
    int*   cnt_s = (int*)  (sm + OFF_CNT);

    const int tid  = threadIdx.x;
    const int lane = tid & 31, warp = tid >> 5;
    const int wn = warp & 3, wm = warp >> 2;   // 4 n-groups x 2 m-groups (32x64)
    const int row0 = blockIdx.x * BM;

    if (tid < 8)  cnt_s[tid] = 0;
    b1s[tid] = b1[tid];
    if (tid < 64) cid_s[tid] = cid[row0 + tid];

    float acc[2][8][4];
    #pragma unroll
    for (int mt = 0; mt < 2; mt++)
        #pragma unroll
        for (int nt = 0; nt < 8; nt++)
            #pragma unroll
            for (int q = 0; q < 4; q++) acc[mt][nt][q] = 0.0f;

    // prologue: stages 0,1
    float4 areg[4];
    cp_B(base, 0, 0, tid);
    asm volatile("cp.async.commit_group;" ::: "memory");
    cp_B(base, 1, BK, tid);
    asm volatile("cp.async.commit_group;" ::: "memory");
    ldgA(areg, x, row0, 0, tid);
    stsA(base + OFF_A(0), areg, tid);
    ldgA(areg, x, row0, 1, tid);
    stsA(base + OFF_A(1), areg, tid);

    int s = 0;
    for (int it = 0; it < NITER; it++) {
        if (it < NITER - 1)
            asm volatile("cp.async.wait_group 1;" ::: "memory");
        else
            asm volatile("cp.async.wait_group 0;" ::: "memory");
        __syncthreads();

        const bool pf = (it + 2 < NITER);
        const int sp = (s + 2 >= 3) ? s - 1 : s + 2;  // (s+2)%3
        if (pf) {
            ldgA(areg, x, row0, it + 2, tid);
            cp_B(base, sp, (it + 2) * BK, tid);
            asm volatile("cp.async.commit_group;" ::: "memory");
        }

        const uint32_t sA = base + OFF_A(s), sB = base + OFF_B(s);
        #pragma unroll
        for (int half = 0; half < 2; half++) {
            #pragma unroll
            for (int kq = 0; kq < 2; kq++) {
                const int ks = half * 2 + kq;
                uint32_t a[2][4];
                const uint32_t abase = sA + (unsigned)(wm * 32 + (lane & 15)) * LDA
                                     + (unsigned)ks * 32 + (unsigned)(lane >> 4) * 16;
                #pragma unroll
                for (int mt = 0; mt < 2; mt++)
                    ldm4(a[mt], abase + (unsigned)(mt * 16) * LDA);
                #pragma unroll
                for (int j = 0; j < 4; j++) {
                    uint32_t b[4];
                    ldm4(b, sB + (unsigned)(wn * 64 + j * 16 + (lane & 15)) * LDA
                              + (unsigned)ks * 32 + (unsigned)(lane >> 4) * 16);
                    #pragma unroll
                    for (int mt = 0; mt < 2; mt++) {
                        mma_bf16(acc[mt][2 * j],     a[mt], b[0], b[2]);
                        mma_bf16(acc[mt][2 * j + 1], a[mt], b[1], b[3]);
                    }
                }
            }
            if (pf && half == 0) stsA(base + OFF_A(sp), areg, tid);
        }
        s = (s + 1 >= 3) ? 0 : s + 1;
    }
    __syncthreads();   // protect hbuf (unioned with stage 0/1) until all reads done

    // epilogue: accum -> smem hbuf
    float* hbuf = (float*)sm;
    #pragma unroll
    for (int mt = 0; mt < 2; mt++)
        #pragma unroll
        for (int nt = 0; nt < 8; nt++) {
            int gm = wm * 32 + mt * 16 + (lane >> 2);
            int gn = wn * 64 + nt * 8 + 2 * (lane & 3);
            hbuf[gm * HLD + gn]           = acc[mt][nt][0];
            hbuf[gm * HLD + gn + 1]       = acc[mt][nt][1];
            hbuf[(gm + 8) * HLD + gn]     = acc[mt][nt][2];
            hbuf[(gm + 8) * HLD + gn + 1] = acc[mt][nt][3];
        }

    // cluster counts (first 2 warps cover 64 rows)
    if (tid < 64) {
        int cidv = cid_s[tid];
        #pragma unroll
        for (int c = 0; c < 8; c++) {
            unsigned m = __ballot_sync(0xffffffffu, cidv == c);
            if (lane == c) atomicAdd(&cnt_s[c], __popc(m));
        }
    }
    __syncthreads();

    // bias + relu + cluster-masked column sums: thread = column
    const float bt = b1s[tid];
    float sacc[NCLUS];
    #pragma unroll
    for (int c = 0; c < NCLUS; c++) sacc[c] = 0.0f;
    #pragma unroll 4
    for (int r = 0; r < 64; r++) {
        float v = fmaxf(hbuf[r * HLD + tid] + bt, 0.0f);
        int cd = cid_s[r];
        #pragma unroll
        for (int c = 0; c < NCLUS; c++) sacc[c] += (cd == c) ? v : 0.0f;
    }
    float* outp = g_scratch + (size_t)blockIdx.x * (NCLUS * DIMH) + tid;
    #pragma unroll
    for (int c = 0; c < NCLUS; c++) outp[c * DIMH] = sacc[c];
    if (tid < 8) g_scnt[blockIdx.x * 8 + tid] = cnt_s[tid];
}

// ---------------------------------------------------------------------------
// K2: reduce 1024 block partials -> g_seg ; counts -> g_cnt
// ---------------------------------------------------------------------------
__global__ __launch_bounds__(256)
void k_reduce()
{
    const int g0 = blockIdx.x * 32;
    const int jj = threadIdx.x & 31;
    const int bs = threadIdx.x >> 5;
    float s = 0.0f;
    #pragma unroll 4
    for (int b = bs; b < NBLK; b += 8)
        s += g_scratch[(size_t)b * (NCLUS * DIMH) + g0 + jj];
    __shared__ float red[8][33];
    __shared__ int   credp[8][9];
    red[bs][jj] = s;
    if (blockIdx.x == 0 && threadIdx.x < 64) {
        int c = threadIdx.x & 7, sl = threadIdx.x >> 3, t = 0;
        for (int b = sl; b < NBLK; b += 8) t += g_scnt[b * 8 + c];
        credp[c][sl] = t;
    }
    __syncthreads();
    if (bs == 0) {
        float t = 0.0f;
        #pragma unroll
        for (int c = 0; c < 8; c++) t += red[c][jj];
        g_seg[g0 + jj] = t;
    }
    if (blockIdx.x == 0 && threadIdx.x < 8) {
        int T = 0;
        #pragma unroll
        for (int sl = 0; sl < 8; sl++) T += credp[threadIdx.x][sl];
        g_cnt[threadIdx.x] = T;
    }
}

// ---------------------------------------------------------------------------
// K3: per-cluster head (mean -> hp -> gated logit), grid 8 x 256
// ---------------------------------------------------------------------------
__global__ __launch_bounds__(256)
void k_head(const float* __restrict__ Wf, const float* __restrict__ bfv,
            const float* __restrict__ Wa, const float* __restrict__ ba,
            const float* __restrict__ Wb, const float* __restrict__ bb,
            const float* __restrict__ Wc)
{
    const int c = blockIdx.x, tid = threadIdx.x, lane = tid & 31;
    __shared__ float hc_s[DIMH];
    __shared__ float hp_s[DIMH];
    __shared__ float wred[8];

    float denom = fmaxf((float)g_cnt[c], 1.0f);
    hc_s[tid] = g_seg[c * DIMH + tid] * (1.0f / denom);
    __syncthreads();

    // hp = relu(Wf hc + bf)
    {
        float a = bfv[tid];
        const float4* w = (const float4*)(Wf + (size_t)tid * DIMH);
        #pragma unroll 8
        for (int k = 0; k < DIMH / 4; k++) {
            float4 wv = w[k];
            a += wv.x * hc_s[4 * k]     + wv.y * hc_s[4 * k + 1]
               + wv.z * hc_s[4 * k + 2] + wv.w * hc_s[4 * k + 3];
        }
        float h = fmaxf(a, 0.0f);
        hp_s[tid] = h;
        g_hp[c * DIMH + tid] = h;
    }
    __syncthreads();

    // gated logit
    float aa = ba[tid], gg = bb[tid];
    const float4* wa = (const float4*)(Wa + (size_t)tid * DIMH);
    const float4* wb = (const float4*)(Wb + (size_t)tid * DIMH);
    #pragma unroll 8
    for (int k = 0; k < DIMH / 4; k++) {
        float4 av = wa[k], bv = wb[k];
        float h0 = hp_s[4 * k], h1 = hp_s[4 * k + 1];
        float h2 = hp_s[4 * k + 2], h3 = hp_s[4 * k + 3];
        aa += av.x * h0 + av.y * h1 + av.z * h2 + av.w * h3;
        gg += bv.x * h0 + bv.y * h1 + bv.z * h2 + bv.w * h3;
    }
    float val = tanhf(aa) * (1.0f / (1.0f + expf(-gg))) * Wc[tid];
    #pragma unroll
    for (int o = 16; o > 0; o >>= 1)
        val += __shfl_xor_sync(0xffffffffu, val, o);
    if (lane == 0) wred[tid >> 5] = val;
    __syncthreads();
    if (tid == 0) {
        float t = 0.0f;
        #pragma unroll
        for (int w = 0; w < 8; w++) t += wred[w];
        g_Ag[c] = t;
    }
}

// ---------------------------------------------------------------------------
// K4: softmax + weighted sum -> out[256]
// ---------------------------------------------------------------------------
__global__ __launch_bounds__(256)
void k_final(const float* __restrict__ bc, float* __restrict__ out)
{
    const int tid = threadIdx.x;
    float l[NCLUS];
    float m = -1e30f;
    #pragma unroll
    for (int c = 0; c < NCLUS; c++) { l[c] = g_Ag[c] + bc[0]; m = fmaxf(m, l[c]); }
    float S = 0.0f;
    #pragma unroll
    for (int c = 0; c < NCLUS; c++) { l[c] = expf(l[c] - m); S += l[c]; }
    float o = 0.0f;
    #pragma unroll
    for (int c = 0; c < NCLUS; c++) o += l[c] * g_hp[c * DIMH + tid];
    out[tid] = o / S;
}

// ---------------------------------------------------------------------------
extern "C" void kernel_launch(void* const* d_in, const int* in_sizes, int n_in,
                              void* d_out, int out_size)
{
    const float* x   = (const float*)d_in[0];
    const int*   cid = (const int*)  d_in[1];
    const float* W1  = (const float*)d_in[2];
    const float* b1  = (const float*)d_in[3];
    const float* Wf  = (const float*)d_in[4];
    const float* bf  = (const float*)d_in[5];
    const float* Wa  = (const float*)d_in[6];
    const float* ba  = (const float*)d_in[7];
    const float* Wb  = (const float*)d_in[8];
    const float* bb  = (const float*)d_in[9];
    const float* Wc  = (const float*)d_in[10];
    const float* bc  = (const float*)d_in[11];

    cudaFuncSetAttribute(k_gemm_seg, cudaFuncAttributeMaxDynamicSharedMemorySize, SMEM_DYN);

    k_w1cvt<<<256, 256>>>(W1);
    k_gemm_seg<<<NBLK, 256, SMEM_DYN>>>(x, cid, b1);
    k_reduce<<<64, 256>>>();
    k_head<<<8, 256>>>(Wf, bf, Wa, ba, Wb, bb, Wc);
    k_final<<<1, 256>>>(bc, (float*)d_out);
}

// round 7
// speedup vs baseline: 1.4152x; 1.4152x over previous
#include <cuda_runtime.h>
#include <cuda_bf16.h>
#include <cstdint>
#include <math.h>

#define NQ     65536
#define DIMIN  1024
#define DIMH   256
#define NCLUS  8
#define BM     128
#define BN     256
#define BK     64
#define NBLK   (NQ / BM)       // 512
#define NITER  (DIMIN / BK)    // 16
#define TGRID  128             // fused tail grid

// smem layout (bytes) -- identical to R5
#define LDA      144
#define STAGE_A  (128 * LDA)   // 18432
#define STAGE_B  (256 * LDA)   // 36864
#define STAGE    (STAGE_A + STAGE_B)
#define OFF_A(s) ((unsigned)(s) * STAGE)
#define OFF_B(s) ((unsigned)(s) * STAGE + STAGE_A)
#define HLD      260
#define OFF_EXTRA 133120u
#define OFF_B1   OFF_EXTRA
#define OFF_CID  (OFF_B1 + 1024u)
#define OFF_CNT  (OFF_CID + 512u)
#define SMEM_DYN (OFF_CNT + 32u)   // ~134.7 KB -> 1 CTA/SM

// ---- device scratch ----
__device__ __nv_bfloat16 g_W1bf[DIMH * DIMIN];        // 512 KB
__device__ float g_scratch[NBLK * NCLUS * DIMH];      // 4 MB
__device__ int   g_scnt[NBLK * NCLUS];
__device__ float g_seg[NCLUS * DIMH];
__device__ int   g_cnt[NCLUS];
__device__ float g_hp[NCLUS * DIMH];
__device__ float g_part[NCLUS * 16];
__device__ unsigned g_barc[3];     // phase barriers (replay-safe: reset at end)
__device__ unsigned g_donec;

// ---- helpers ----
__device__ __forceinline__ uint32_t smem_u32(const void* p) {
    uint32_t a;
    asm("{ .reg .u64 t; cvta.to.shared.u64 t, %1; cvt.u32.u64 %0, t; }" : "=r"(a) : "l"(p));
    return a;
}

__device__ __forceinline__ void ldm4(uint32_t* r, uint32_t addr) {
    asm volatile("ldmatrix.sync.aligned.m8n8.x4.shared.b16 {%0,%1,%2,%3}, [%4];"
                 : "=r"(r[0]), "=r"(r[1]), "=r"(r[2]), "=r"(r[3]) : "r"(addr));
}

__device__ __forceinline__ void mma_bf16(float* d, const uint32_t* a,
                                         uint32_t b0, uint32_t b1) {
    asm volatile("mma.sync.aligned.m16n8k16.row.col.f32.bf16.bf16.f32 "
                 "{%0,%1,%2,%3}, {%4,%5,%6,%7}, {%8,%9}, {%0,%1,%2,%3};"
                 : "+f"(d[0]), "+f"(d[1]), "+f"(d[2]), "+f"(d[3])
                 : "r"(a[0]), "r"(a[1]), "r"(a[2]), "r"(a[3]), "r"(b0), "r"(b1));
}

__device__ __forceinline__ void cp_B(uint32_t base, int s, int k0, int tid) {
    uint32_t dst = base + OFF_B(s);
    const char* src = (const char*)g_W1bf + (size_t)k0 * 2;
    #pragma unroll
    for (int i = 0; i < 8; i++) {
        int c  = tid + 256 * i;
        int n  = c >> 3, kc = c & 7;
        uint32_t d = dst + (unsigned)n * LDA + (unsigned)kc * 16;
        const void* g = src + (size_t)n * (DIMIN * 2) + kc * 16;
        asm volatile("cp.async.cg.shared.global [%0], [%1], 16;" :: "r"(d), "l"(g));
    }
}

__device__ __forceinline__ void ldgA(float4* areg, const float* x,
                                     int row0, int it, int tid, int h) {
    const int r0 = h * 64 + (tid >> 4), fc = tid & 15;
    const float* p = x + (size_t)(row0 + r0) * DIMIN + it * BK + fc * 4;
    #pragma unroll
    for (int i = 0; i < 4; i++)
        areg[i] = *(const float4*)(p + (size_t)(16 * i) * DIMIN);
}

__device__ __forceinline__ void stsA(uint32_t sA, const float4* areg, int tid, int h) {
    const int r0 = h * 64 + (tid >> 4), fc = tid & 15;
    #pragma unroll
    for (int i = 0; i < 4; i++) {
        __nv_bfloat162 lo = __floats2bfloat162_rn(areg[i].x, areg[i].y);
        __nv_bfloat162 hi = __floats2bfloat162_rn(areg[i].z, areg[i].w);
        uint32_t u0 = *(uint32_t*)&lo, u1 = *(uint32_t*)&hi;
        uint32_t d = sA + (unsigned)(r0 + 16 * i) * LDA + (unsigned)fc * 8;
        asm volatile("st.shared.v2.b32 [%0], {%1,%2};" :: "r"(d), "r"(u0), "r"(u1));
    }
}

// ---------------------------------------------------------------------------
// K0: W1 fp32 -> bf16
// ---------------------------------------------------------------------------
__global__ __launch_bounds__(256)
void k_w1cvt(const float* __restrict__ W1) {
    int i = (blockIdx.x * 256 + threadIdx.x) * 4;
    float4 v = *(const float4*)(W1 + i);
    __nv_bfloat162 lo = __floats2bfloat162_rn(v.x, v.y);
    __nv_bfloat162 hi = __floats2bfloat162_rn(v.z, v.w);
    uint2 u;
    u.x = *(uint32_t*)&lo;
    u.y = *(uint32_t*)&hi;
    *(uint2*)&g_W1bf[i] = u;
}

// ---------------------------------------------------------------------------
// K1: bf16 mma GEMM 128x256 per CTA, 256 thr (warp tile 64x64)  -- R5 proven
// ---------------------------------------------------------------------------
__global__ __launch_bounds__(256, 1)
void k_gemm_seg(const float* __restrict__ x, const int* __restrict__ cid,
                const float* __restrict__ b1)
{
    extern __shared__ char sm[];
    const uint32_t base = smem_u32(sm);
    float* b1s   = (float*)(sm + OFF_B1);
    int*   cid_s = (int*)  (sm + OFF_CID);
    int*   cnt_s = (int*)  (sm + OFF_CNT);

    const int tid  = threadIdx.x;
    const int lane = tid & 31, warp = tid >> 5;
    const int wn = warp & 3, wm = warp >> 2;
    const int row0 = blockIdx.x * BM;

    if (tid < 8)   cnt_s[tid] = 0;
    b1s[tid] = b1[tid];
    if (tid < 128) cid_s[tid] = cid[row0 + tid];

    float acc[4][8][4];
    #pragma unroll
    for (int mt = 0; mt < 4; mt++)
        #pragma unroll
        for (int nt = 0; nt < 8; nt++)
            #pragma unroll
            for (int q = 0; q < 4; q++) acc[mt][nt][q] = 0.0f;

    float4 areg[4];
    cp_B(base, 0, 0, tid);
    asm volatile("cp.async.commit_group;" ::: "memory");
    ldgA(areg, x, row0, 0, tid, 0);
    stsA(base + OFF_A(0), areg, tid, 0);
    ldgA(areg, x, row0, 0, tid, 1);
    stsA(base + OFF_A(0), areg, tid, 1);
    asm volatile("cp.async.wait_group 0;" ::: "memory");
    __syncthreads();

    for (int it = 0; it < NITER; it++) {
        const int s = it & 1;
        const bool nxt = (it + 1 < NITER);
        if (nxt) {
            cp_B(base, s ^ 1, (it + 1) * BK, tid);
            asm volatile("cp.async.commit_group;" ::: "memory");
            ldgA(areg, x, row0, it + 1, tid, 0);
        }
        const uint32_t sA = base + OFF_A(s), sB = base + OFF_B(s);

        #pragma unroll
        for (int half = 0; half < 2; half++) {
            #pragma unroll
            for (int kq = 0; kq < 2; kq++) {
                const int ks = half * 2 + kq;
                uint32_t a[4][4];
                const uint32_t abase = sA + (unsigned)(wm * 64 + (lane & 15)) * LDA
                                     + (unsigned)ks * 32 + (unsigned)(lane >> 4) * 16;
                #pragma unroll
                for (int mt = 0; mt < 4; mt++)
                    ldm4(a[mt], abase + (unsigned)(mt * 16) * LDA);
                #pragma unroll
                for (int j = 0; j < 4; j++) {
                    uint32_t b[4];
                    ldm4(b, sB + (unsigned)(wn * 64 + j * 16 + (lane & 15)) * LDA
                              + (unsigned)ks * 32 + (unsigned)(lane >> 4) * 16);
                    #pragma unroll
                    for (int mt = 0; mt < 4; mt++) {
                        mma_bf16(acc[mt][2 * j],     a[mt], b[0], b[2]);
                        mma_bf16(acc[mt][2 * j + 1], a[mt], b[1], b[3]);
                    }
                }
            }
            if (nxt) {
                stsA(base + OFF_A(s ^ 1), areg, tid, half);
                if (half == 0) ldgA(areg, x, row0, it + 1, tid, 1);
                else asm volatile("cp.async.wait_group 0;" ::: "memory");
            }
        }
        __syncthreads();
    }

    float* hbuf = (float*)sm;
    #pragma unroll
    for (int mt = 0; mt < 4; mt++)
        #pragma unroll
        for (int nt = 0; nt < 8; nt++) {
            int gm = wm * 64 + mt * 16 + (lane >> 2);
            int gn = wn * 64 + nt * 8 + 2 * (lane & 3);
            hbuf[gm * HLD + gn]           = acc[mt][nt][0];
            hbuf[gm * HLD + gn + 1]       = acc[mt][nt][1];
            hbuf[(gm + 8) * HLD + gn]     = acc[mt][nt][2];
            hbuf[(gm + 8) * HLD + gn + 1] = acc[mt][nt][3];
        }

    if (tid < 128) {
        int cidv = cid_s[tid];
        #pragma unroll
        for (int c = 0; c < 8; c++) {
            unsigned m = __ballot_sync(0xffffffffu, cidv == c);
            if (lane == c) atomicAdd(&cnt_s[c], __popc(m));
        }
    }
    __syncthreads();

    const float bt = b1s[tid];
    float sacc[NCLUS];
    #pragma unroll
    for (int c = 0; c < NCLUS; c++) sacc[c] = 0.0f;
    #pragma unroll 4
    for (int r = 0; r < 128; r++) {
        float v = fmaxf(hbuf[r * HLD + tid] + bt, 0.0f);
        int cd = cid_s[r];
        #pragma unroll
        for (int c = 0; c < NCLUS; c++) sacc[c] += (cd == c) ? v : 0.0f;
    }
    float* outp = g_scratch + (size_t)blockIdx.x * (NCLUS * DIMH) + tid;
    #pragma unroll
    for (int c = 0; c < NCLUS; c++) outp[c * DIMH] = sacc[c];
    if (tid < 8) g_scnt[blockIdx.x * 8 + tid] = cnt_s[tid];
}

// ---------------------------------------------------------------------------
// K2: fused tail -- grid TGRID(128) x 256, device-wide phase barriers
// ---------------------------------------------------------------------------
__device__ __forceinline__ void grid_bar(int p) {
    __syncthreads();
    if (threadIdx.x == 0) {
        __threadfence();
        atomicAdd(&g_barc[p], 1u);
        while (atomicAdd(&g_barc[p], 0u) < (unsigned)TGRID) __nanosleep(64);
        __threadfence();
    }
    __syncthreads();
}

__global__ __launch_bounds__(256)
void k_tail(const float* __restrict__ Wf, const float* __restrict__ bfv,
            const float* __restrict__ Wa, const float* __restrict__ ba,
            const float* __restrict__ Wb, const float* __restrict__ bb,
            const float* __restrict__ Wc, const float* __restrict__ bc,
            float* __restrict__ out)
{
    const int b = blockIdx.x, tid = threadIdx.x;
    __shared__ float red[16][17];
    __shared__ int   credp[8][9];
    __shared__ float hc_s[DIMH];
    __shared__ float hp_s[DIMH];
    __shared__ float rowred[16];
    __shared__ float partsm[128];
    __shared__ float logits[8];

    // ---- Phase A: reduce 512 partials -> g_seg (16 cols per block) + counts
    {
        const int g0 = b * 16;
        const int cidx = tid & 15, slice = tid >> 4;
        float s = 0.0f;
        #pragma unroll 8
        for (int pb = slice; pb < NBLK; pb += 16)
            s += g_scratch[(size_t)pb * (NCLUS * DIMH) + g0 + cidx];
        red[slice][cidx] = s;
        __syncthreads();
        if (tid < 16) {
            float t = 0.0f;
            #pragma unroll
            for (int k = 0; k < 16; k++) t += red[k][tid];
            g_seg[g0 + tid] = t;
        }
        if (b == 0 && tid < 64) {
            int c = tid & 7, sl = tid >> 3, t = 0;
            for (int pb = sl; pb < NBLK; pb += 8) t += g_scnt[pb * 8 + c];
            credp[c][sl] = t;
        }
        __syncthreads();
        if (b == 0 && tid < 8) {
            int T = 0;
            #pragma unroll
            for (int sl = 0; sl < 8; sl++) T += credp[tid][sl];
            g_cnt[tid] = T;
        }
    }
    grid_bar(0);

    // ---- Phase B: hp = relu(Wf hc + bf);  block = (cluster, 16-row group)
    const int c  = b >> 4, og = b & 15;
    {
        float denom = fmaxf((float)g_cnt[c], 1.0f);
        hc_s[tid] = g_seg[c * DIMH + tid] * (1.0f / denom);
        __syncthreads();

        const int row = og * 16 + (tid >> 4);
        const int k0  = (tid & 15) * 16;
        const float4* w = (const float4*)(Wf + (size_t)row * DIMH + k0);
        float a = 0.0f;
        #pragma unroll
        for (int k = 0; k < 4; k++) {
            float4 wv = w[k];
            a += wv.x * hc_s[k0 + 4 * k]     + wv.y * hc_s[k0 + 4 * k + 1]
               + wv.z * hc_s[k0 + 4 * k + 2] + wv.w * hc_s[k0 + 4 * k + 3];
        }
        #pragma unroll
        for (int o = 8; o > 0; o >>= 1)
            a += __shfl_xor_sync(0xffffffffu, a, o);
        if ((tid & 15) == 0)
            g_hp[c * DIMH + row] = fmaxf(a + bfv[row], 0.0f);
    }
    grid_bar(1);

    // ---- Phase C: gated logit partials
    {
        hp_s[tid] = g_hp[c * DIMH + tid];
        __syncthreads();

        const int row = og * 16 + (tid >> 4);
        const int k0  = (tid & 15) * 16;
        const float4* wa = (const float4*)(Wa + (size_t)row * DIMH + k0);
        const float4* wb = (const float4*)(Wb + (size_t)row * DIMH + k0);
        float aa = 0.0f, gg = 0.0f;
        #pragma unroll
        for (int k = 0; k < 4; k++) {
            float4 av = wa[k], bv = wb[k];
            float h0 = hp_s[k0 + 4 * k], h1 = hp_s[k0 + 4 * k + 1];
            float h2 = hp_s[k0 + 4 * k + 2], h3 = hp_s[k0 + 4 * k + 3];
            aa += av.x * h0 + av.y * h1 + av.z * h2 + av.w * h3;
            gg += bv.x * h0 + bv.y * h1 + bv.z * h2 + bv.w * h3;
        }
        #pragma unroll
        for (int o = 8; o > 0; o >>= 1) {
            aa += __shfl_xor_sync(0xffffffffu, aa, o);
            gg += __shfl_xor_sync(0xffffffffu, gg, o);
        }
        if ((tid & 15) == 0) {
            int row_l = tid >> 4;
            float a2 = aa + ba[row], g2 = gg + bb[row];
            rowred[row_l] = tanhf(a2) * (1.0f / (1.0f + expf(-g2))) * Wc[row];
        }
        __syncthreads();
        if (tid == 0) {
            float t = 0.0f;
            #pragma unroll
            for (int r = 0; r < 16; r++) t += rowred[r];
            g_part[c * 16 + og] = t;
        }
    }
    grid_bar(2);

    // ---- Phase D (block 0): softmax + weighted sum -> out
    if (b == 0) {
        if (tid < 128) partsm[tid] = g_part[tid];
        __syncthreads();
        if (tid < 8) {
            float t = bc[0];
            #pragma unroll
            for (int k = 0; k < 16; k++) t += partsm[tid * 16 + k];
            logits[tid] = t;
        }
        __syncthreads();
        float l[NCLUS], m = -1e30f;
        #pragma unroll
        for (int cc = 0; cc < NCLUS; cc++) { l[cc] = logits[cc]; m = fmaxf(m, l[cc]); }
        float S = 0.0f;
        #pragma unroll
        for (int cc = 0; cc < NCLUS; cc++) { l[cc] = expf(l[cc] - m); S += l[cc]; }
        float o = 0.0f;
        #pragma unroll
        for (int cc = 0; cc < NCLUS; cc++) o += l[cc] * g_hp[cc * DIMH + tid];
        out[tid] = o / S;
        __syncthreads();
        // replay-safe reset: wait for all other blocks to fully exit barriers
        if (tid == 0) {
            while (atomicAdd(&g_donec, 0u) < (unsigned)(TGRID - 1)) __nanosleep(64);
            g_barc[0] = 0; g_barc[1] = 0; g_barc[2] = 0; g_donec = 0;
            __threadfence();
        }
    } else {
        if (tid == 0) { __threadfence(); atomicAdd(&g_donec, 1u); }
    }
}

// ---------------------------------------------------------------------------
extern "C" void kernel_launch(void* const* d_in, const int* in_sizes, int n_in,
                              void* d_out, int out_size)
{
    const float* x   = (const float*)d_in[0];
    const int*   cid = (const int*)  d_in[1];
    const float* W1  = (const float*)d_in[2];
    const float* b1  = (const float*)d_in[3];
    const float* Wf  = (const float*)d_in[4];
    const float* bf  = (const float*)d_in[5];
    const float* Wa  = (const float*)d_in[6];
    const float* ba  = (const float*)d_in[7];
    const float* Wb  = (const float*)d_in[8];
    const float* bb  = (const float*)d_in[9];
    const float* Wc  = (const float*)d_in[10];
    const float* bc  = (const float*)d_in[11];

    cudaFuncSetAttribute(k_gemm_seg, cudaFuncAttributeMaxDynamicSharedMemorySize, SMEM_DYN);

    k_w1cvt<<<256, 256>>>(W1);
    k_gemm_seg<<<NBLK, 256, SMEM_DYN>>>(x, cid, b1);
    k_tail<<<TGRID, 256>>>(Wf, bf, Wa, ba, Wb, bb, Wc, bc, (float*)d_out);
}

// round 8
// speedup vs baseline: 1.4206x; 1.0038x over previous
#include <cuda_runtime.h>
#include <cuda_bf16.h>
#include <cstdint>
#include <math.h>

#define NQ     65536
#define DIMIN  1024
#define DIMH   256
#define NCLUS  8
#define BM     128
#define BN     256
#define BK     64
#define NBLK   (NQ / BM)       // 512
#define NITER  (DIMIN / BK)    // 16
#define TGRID  128
#define SEG_SCALE 4294967296.0   // 2^32

// smem layout (bytes) -- identical to R5/R7
#define LDA      144
#define STAGE_A  (128 * LDA)
#define STAGE_B  (256 * LDA)
#define STAGE    (STAGE_A + STAGE_B)
#define OFF_A(s) ((unsigned)(s) * STAGE)
#define OFF_B(s) ((unsigned)(s) * STAGE + STAGE_A)
#define HLD      260
#define OFF_EXTRA 133120u
#define OFF_B1   OFF_EXTRA
#define OFF_CID  (OFF_B1 + 1024u)
#define OFF_CNT  (OFF_CID + 512u)
#define SMEM_DYN (OFF_CNT + 32u)   // ~134.7 KB -> 1 CTA/SM

// ---- device scratch ----
__device__ __nv_bfloat16 g_W1bf[DIMH * DIMIN];        // 512 KB
__device__ unsigned long long g_segi[NCLUS * DIMH];   // fixed-point seg sums
__device__ unsigned g_cnti[NCLUS];
__device__ float g_hp[NCLUS * DIMH];
__device__ float g_part[NCLUS * 16];
__device__ unsigned g_barc[2];
__device__ unsigned g_donec;

// ---- helpers ----
__device__ __forceinline__ uint32_t smem_u32(const void* p) {
    uint32_t a;
    asm("{ .reg .u64 t; cvta.to.shared.u64 t, %1; cvt.u32.u64 %0, t; }" : "=r"(a) : "l"(p));
    return a;
}

__device__ __forceinline__ void ldm4(uint32_t* r, uint32_t addr) {
    asm volatile("ldmatrix.sync.aligned.m8n8.x4.shared.b16 {%0,%1,%2,%3}, [%4];"
                 : "=r"(r[0]), "=r"(r[1]), "=r"(r[2]), "=r"(r[3]) : "r"(addr));
}

__device__ __forceinline__ void mma_bf16(float* d, const uint32_t* a,
                                         uint32_t b0, uint32_t b1) {
    asm volatile("mma.sync.aligned.m16n8k16.row.col.f32.bf16.bf16.f32 "
                 "{%0,%1,%2,%3}, {%4,%5,%6,%7}, {%8,%9}, {%0,%1,%2,%3};"
                 : "+f"(d[0]), "+f"(d[1]), "+f"(d[2]), "+f"(d[3])
                 : "r"(a[0]), "r"(a[1]), "r"(a[2]), "r"(a[3]), "r"(b0), "r"(b1));
}

__device__ __forceinline__ void cp_B(uint32_t base, int s, int k0, int tid) {
    uint32_t dst = base + OFF_B(s);
    const char* src = (const char*)g_W1bf + (size_t)k0 * 2;
    #pragma unroll
    for (int i = 0; i < 8; i++) {
        int c  = tid + 256 * i;
        int n  = c >> 3, kc = c & 7;
        uint32_t d = dst + (unsigned)n * LDA + (unsigned)kc * 16;
        const void* g = src + (size_t)n * (DIMIN * 2) + kc * 16;
        asm volatile("cp.async.cg.shared.global [%0], [%1], 16;" :: "r"(d), "l"(g));
    }
}

__device__ __forceinline__ void ldgA(float4* areg, const float* x,
                                     int row0, int it, int tid, int h) {
    const int r0 = h * 64 + (tid >> 4), fc = tid & 15;
    const float* p = x + (size_t)(row0 + r0) * DIMIN + it * BK + fc * 4;
    #pragma unroll
    for (int i = 0; i < 4; i++)
        areg[i] = *(const float4*)(p + (size_t)(16 * i) * DIMIN);
}

__device__ __forceinline__ void stsA(uint32_t sA, const float4* areg, int tid, int h) {
    const int r0 = h * 64 + (tid >> 4), fc = tid & 15;
    #pragma unroll
    for (int i = 0; i < 4; i++) {
        __nv_bfloat162 lo = __floats2bfloat162_rn(areg[i].x, areg[i].y);
        __nv_bfloat162 hi = __floats2bfloat162_rn(areg[i].z, areg[i].w);
        uint32_t u0 = *(uint32_t*)&lo, u1 = *(uint32_t*)&hi;
        uint32_t d = sA + (unsigned)(r0 + 16 * i) * LDA + (unsigned)fc * 8;
        asm volatile("st.shared.v2.b32 [%0], {%1,%2};" :: "r"(d), "r"(u0), "r"(u1));
    }
}

// ---------------------------------------------------------------------------
// K0: W1 fp32 -> bf16  + zero the deterministic accumulators for this run
// ---------------------------------------------------------------------------
__global__ __launch_bounds__(256)
void k_w1cvt(const float* __restrict__ W1) {
    int j = blockIdx.x * 256 + threadIdx.x;
    int i = j * 4;
    float4 v = *(const float4*)(W1 + i);
    __nv_bfloat162 lo = __floats2bfloat162_rn(v.x, v.y);
    __nv_bfloat162 hi = __floats2bfloat162_rn(v.z, v.w);
    uint2 u;
    u.x = *(uint32_t*)&lo;
    u.y = *(uint32_t*)&hi;
    *(uint2*)&g_W1bf[i] = u;
    if (j < NCLUS * DIMH) g_segi[j] = 0ull;
    if (j < NCLUS)        g_cnti[j] = 0u;
}

// ---------------------------------------------------------------------------
// K1: bf16 mma GEMM 128x256 per CTA (R5-proven mainloop) +
//     fused bias+relu+cluster sums -> deterministic u64 atomics
// ---------------------------------------------------------------------------
__global__ __launch_bounds__(256, 1)
void k_gemm_seg(const float* __restrict__ x, const int* __restrict__ cid,
                const float* __restrict__ b1)
{
    extern __shared__ char sm[];
    const uint32_t base = smem_u32(sm);
    float* b1s   = (float*)(sm + OFF_B1);
    int*   cid_s = (int*)  (sm + OFF_CID);
    int*   cnt_s = (int*)  (sm + OFF_CNT);

    const int tid  = threadIdx.x;
    const int lane = tid & 31, warp = tid >> 5;
    const int wn = warp & 3, wm = warp >> 2;
    const int row0 = blockIdx.x * BM;

    if (tid < 8)   cnt_s[tid] = 0;
    b1s[tid] = b1[tid];
    if (tid < 128) cid_s[tid] = cid[row0 + tid];

    float acc[4][8][4];
    #pragma unroll
    for (int mt = 0; mt < 4; mt++)
        #pragma unroll
        for (int nt = 0; nt < 8; nt++)
            #pragma unroll
            for (int q = 0; q < 4; q++) acc[mt][nt][q] = 0.0f;

    float4 areg[4];
    cp_B(base, 0, 0, tid);
    asm volatile("cp.async.commit_group;" ::: "memory");
    ldgA(areg, x, row0, 0, tid, 0);
    stsA(base + OFF_A(0), areg, tid, 0);
    ldgA(areg, x, row0, 0, tid, 1);
    stsA(base + OFF_A(0), areg, tid, 1);
    asm volatile("cp.async.wait_group 0;" ::: "memory");
    __syncthreads();

    for (int it = 0; it < NITER; it++) {
        const int s = it & 1;
        const bool nxt = (it + 1 < NITER);
        if (nxt) {
            cp_B(base, s ^ 1, (it + 1) * BK, tid);
            asm volatile("cp.async.commit_group;" ::: "memory");
            ldgA(areg, x, row0, it + 1, tid, 0);
        }
        const uint32_t sA = base + OFF_A(s), sB = base + OFF_B(s);

        #pragma unroll
        for (int half = 0; half < 2; half++) {
            #pragma unroll
            for (int kq = 0; kq < 2; kq++) {
                const int ks = half * 2 + kq;
                uint32_t a[4][4];
                const uint32_t abase = sA + (unsigned)(wm * 64 + (lane & 15)) * LDA
                                     + (unsigned)ks * 32 + (unsigned)(lane >> 4) * 16;
                #pragma unroll
                for (int mt = 0; mt < 4; mt++)
                    ldm4(a[mt], abase + (unsigned)(mt * 16) * LDA);
                #pragma unroll
                for (int j = 0; j < 4; j++) {
                    uint32_t b[4];
                    ldm4(b, sB + (unsigned)(wn * 64 + j * 16 + (lane & 15)) * LDA
                              + (unsigned)ks * 32 + (unsigned)(lane >> 4) * 16);
                    #pragma unroll
                    for (int mt = 0; mt < 4; mt++) {
                        mma_bf16(acc[mt][2 * j],     a[mt], b[0], b[2]);
                        mma_bf16(acc[mt][2 * j + 1], a[mt], b[1], b[3]);
                    }
                }
            }
            if (nxt) {
                stsA(base + OFF_A(s ^ 1), areg, tid, half);
                if (half == 0) ldgA(areg, x, row0, it + 1, tid, 1);
                else asm volatile("cp.async.wait_group 0;" ::: "memory");
            }
        }
        __syncthreads();
    }

    float* hbuf = (float*)sm;
    #pragma unroll
    for (int mt = 0; mt < 4; mt++)
        #pragma unroll
        for (int nt = 0; nt < 8; nt++) {
            int gm = wm * 64 + mt * 16 + (lane >> 2);
            int gn = wn * 64 + nt * 8 + 2 * (lane & 3);
            hbuf[gm * HLD + gn]           = acc[mt][nt][0];
            hbuf[gm * HLD + gn + 1]       = acc[mt][nt][1];
            hbuf[(gm + 8) * HLD + gn]     = acc[mt][nt][2];
            hbuf[(gm + 8) * HLD + gn + 1] = acc[mt][nt][3];
        }

    if (tid < 128) {
        int cidv = cid_s[tid];
        #pragma unroll
        for (int c = 0; c < 8; c++) {
            unsigned m = __ballot_sync(0xffffffffu, cidv == c);
            if (lane == c) atomicAdd(&cnt_s[c], __popc(m));
        }
    }
    __syncthreads();

    const float bt = b1s[tid];
    float sacc[NCLUS];
    #pragma unroll
    for (int c = 0; c < NCLUS; c++) sacc[c] = 0.0f;
    #pragma unroll 4
    for (int r = 0; r < 128; r++) {
        float v = fmaxf(hbuf[r * HLD + tid] + bt, 0.0f);
        int cd = cid_s[r];
        #pragma unroll
        for (int c = 0; c < NCLUS; c++) sacc[c] += (cd == c) ? v : 0.0f;
    }
    // deterministic fixed-point accumulation (v >= 0)
    #pragma unroll
    for (int c = 0; c < NCLUS; c++) {
        unsigned long long q = (unsigned long long)llrint((double)sacc[c] * SEG_SCALE);
        atomicAdd(&g_segi[c * DIMH + tid], q);
    }
    if (tid < 8) atomicAdd(&g_cnti[tid], (unsigned)cnt_s[tid]);
}

// ---------------------------------------------------------------------------
// K2: fused tail -- grid 128 x 256 (8 clusters x 16 row-groups)
// ---------------------------------------------------------------------------
__device__ __forceinline__ void grid_bar(int p) {
    __syncthreads();
    if (threadIdx.x == 0) {
        __threadfence();
        atomicAdd(&g_barc[p], 1u);
        while (atomicAdd(&g_barc[p], 0u) < (unsigned)TGRID) __nanosleep(64);
        __threadfence();
    }
    __syncthreads();
}

__global__ __launch_bounds__(256)
void k_tail(const float* __restrict__ Wf, const float* __restrict__ bfv,
            const float* __restrict__ Wa, const float* __restrict__ ba,
            const float* __restrict__ Wb, const float* __restrict__ bb,
            const float* __restrict__ Wc, const float* __restrict__ bc,
            float* __restrict__ out)
{
    const int b = blockIdx.x, tid = threadIdx.x;
    const int c = b >> 4, og = b & 15;
    __shared__ float hc_s[DIMH];
    __shared__ float hp_s[DIMH];
    __shared__ float rowred[16];
    __shared__ float partsm[128];
    __shared__ float logits[8];

    // ---- Phase B: hp = relu(Wf hc + bf)
    {
        float denom = fmaxf((float)g_cnti[c], 1.0f);
        float segv = (float)((double)g_segi[c * DIMH + tid] * (1.0 / SEG_SCALE));
        hc_s[tid] = segv * (1.0f / denom);
        __syncthreads();

        const int row = og * 16 + (tid >> 4);
        const int k0  = (tid & 15) * 16;
        const float4* w = (const float4*)(Wf + (size_t)row * DIMH + k0);
        float a = 0.0f;
        #pragma unroll
        for (int k = 0; k < 4; k++) {
            float4 wv = w[k];
            a += wv.x * hc_s[k0 + 4 * k]     + wv.y * hc_s[k0 + 4 * k + 1]
               + wv.z * hc_s[k0 + 4 * k + 2] + wv.w * hc_s[k0 + 4 * k + 3];
        }
        #pragma unroll
        for (int o = 8; o > 0; o >>= 1)
            a += __shfl_xor_sync(0xffffffffu, a, o);
        if ((tid & 15) == 0)
            g_hp[c * DIMH + row] = fmaxf(a + bfv[row], 0.0f);
    }
    grid_bar(0);

    // ---- Phase C: gated logit partials
    {
        hp_s[tid] = g_hp[c * DIMH + tid];
        __syncthreads();

        const int row = og * 16 + (tid >> 4);
        const int k0  = (tid & 15) * 16;
        const float4* wa = (const float4*)(Wa + (size_t)row * DIMH + k0);
        const float4* wb = (const float4*)(Wb + (size_t)row * DIMH + k0);
        float aa = 0.0f, gg = 0.0f;
        #pragma unroll
        for (int k = 0; k < 4; k++) {
            float4 av = wa[k], bv = wb[k];
            float h0 = hp_s[k0 + 4 * k], h1 = hp_s[k0 + 4 * k + 1];
            float h2 = hp_s[k0 + 4 * k + 2], h3 = hp_s[k0 + 4 * k + 3];
            aa += av.x * h0 + av.y * h1 + av.z * h2 + av.w * h3;
            gg += bv.x * h0 + bv.y * h1 + bv.z * h2 + bv.w * h3;
        }
        #pragma unroll
        for (int o = 8; o > 0; o >>= 1) {
            aa += __shfl_xor_sync(0xffffffffu, aa, o);
            gg += __shfl_xor_sync(0xffffffffu, gg, o);
        }
        if ((tid & 15) == 0) {
            int row_l = tid >> 4;
            float a2 = aa + ba[row], g2 = gg + bb[row];
            rowred[row_l] = tanhf(a2) * (1.0f / (1.0f + expf(-g2))) * Wc[row];
        }
        __syncthreads();
        if (tid == 0) {
            float t = 0.0f;
            #pragma unroll
            for (int r = 0; r < 16; r++) t += rowred[r];
            g_part[c * 16 + og] = t;
        }
    }
    grid_bar(1);

    // ---- Phase D (block 0): softmax + weighted sum -> out, then reset
    if (b == 0) {
        if (tid < 128) partsm[tid] = g_part[tid];
        __syncthreads();
        if (tid < 8) {
            float t = bc[0];
            #pragma unroll
            for (int k = 0; k < 16; k++) t += partsm[tid * 16 + k];
            logits[tid] = t;
        }
        __syncthreads();
        float l[NCLUS], m = -1e30f;
        #pragma unroll
        for (int cc = 0; cc < NCLUS; cc++) { l[cc] = logits[cc]; m = fmaxf(m, l[cc]); }
        float S = 0.0f;
        #pragma unroll
        for (int cc = 0; cc < NCLUS; cc++) { l[cc] = expf(l[cc] - m); S += l[cc]; }
        float o = 0.0f;
        #pragma unroll
        for (int cc = 0; cc < NCLUS; cc++) o += l[cc] * g_hp[cc * DIMH + tid];
        out[tid] = o / S;
        __syncthreads();
        if (tid == 0) {
            while (atomicAdd(&g_donec, 0u) < (unsigned)(TGRID - 1)) __nanosleep(64);
            g_barc[0] = 0; g_barc[1] = 0; g_donec = 0;
            __threadfence();
        }
    } else {
        if (tid == 0) { __threadfence(); atomicAdd(&g_donec, 1u); }
    }
}

// ---------------------------------------------------------------------------
extern "C" void kernel_launch(void* const* d_in, const int* in_sizes, int n_in,
                              void* d_out, int out_size)
{
    const float* x   = (const float*)d_in[0];
    const int*   cid = (const int*)  d_in[1];
    const float* W1  = (const float*)d_in[2];
    const float* b1  = (const float*)d_in[3];
    const float* Wf  = (const float*)d_in[4];
    const float* bf  = (const float*)d_in[5];
    const float* Wa  = (const float*)d_in[6];
    const float* ba  = (const float*)d_in[7];
    const float* Wb  = (const float*)d_in[8];
    const float* bb  = (const float*)d_in[9];
    const float* Wc  = (const float*)d_in[10];
    const float* bc  = (const float*)d_in[11];

    cudaFuncSetAttribute(k_gemm_seg, cudaFuncAttributeMaxDynamicSharedMemorySize, SMEM_DYN);

    k_w1cvt<<<256, 256>>>(W1);
    k_gemm_seg<<<NBLK, 256, SMEM_DYN>>>(x, cid, b1);
    k_tail<<<TGRID, 256>>>(Wf, bf, Wa, ba, Wb, bb, Wc, bc, (float*)d_out);
}

// round 12
// speedup vs baseline: 1.4784x; 1.0406x over previous
#include <cuda_runtime.h>
#include <cuda_bf16.h>
#include <cstdint>
#include <math.h>

#define NQ     65536
#define DIMIN  1024
#define DIMH   256
#define NCLUS  8
#define BM     128
#define BN     256
#define BK     64
#define NTILE  (NQ / BM)       // 512 tiles
#define FULLT  444             // 148*3 full tiles
#define NSPLIT (NTILE - FULLT) // 68 split tiles
#define NGRID  (FULLT + 2 * NSPLIT)  // 580
#define NITER  (DIMIN / BK)    // 16
#define TGRID  128
#define SEG_SCALE 4294967296.0

// smem layout (bytes)
#define LDA      144
#define STAGE_A  (128 * LDA)
#define STAGE_B  (256 * LDA)
#define STAGE    (STAGE_A + STAGE_B)
#define OFF_A(s) ((unsigned)(s) * STAGE)
#define OFF_B(s) ((unsigned)(s) * STAGE + STAGE_A)
#define HLD      260
#define OFF_EXTRA 133120u
#define OFF_B1   OFF_EXTRA
#define OFF_CID  (OFF_B1 + 1024u)
#define OFF_CNT  (OFF_CID + 512u)
#define OFF_FLG  (OFF_CNT + 32u)
#define SMEM_DYN (OFF_FLG + 16u)

// ---- device scratch ----
__device__ __nv_bfloat16 g_W1bf[DIMH * DIMIN];          // 512 KB
__device__ float g_comb[NSPLIT * 2 * 32768];            // 17.8 MB split-K halves
__device__ unsigned g_tick[NSPLIT];
__device__ unsigned long long g_segi[NCLUS * DIMH];
__device__ unsigned g_cnti[NCLUS];
__device__ float g_hp[NCLUS * DIMH];
__device__ float g_part[NCLUS * 16];
__device__ unsigned g_barc[2];
__device__ unsigned g_donec;

// ---- helpers ----
__device__ __forceinline__ uint32_t smem_u32(const void* p) {
    uint32_t a;
    asm("{ .reg .u64 t; cvta.to.shared.u64 t, %1; cvt.u32.u64 %0, t; }" : "=r"(a) : "l"(p));
    return a;
}

__device__ __forceinline__ void ldm4(uint32_t* r, uint32_t addr) {
    asm volatile("ldmatrix.sync.aligned.m8n8.x4.shared.b16 {%0,%1,%2,%3}, [%4];"
                 : "=r"(r[0]), "=r"(r[1]), "=r"(r[2]), "=r"(r[3]) : "r"(addr));
}

__device__ __forceinline__ void mma_bf16(float* d, const uint32_t* a,
                                         uint32_t b0, uint32_t b1) {
    asm volatile("mma.sync.aligned.m16n8k16.row.col.f32.bf16.bf16.f32 "
                 "{%0,%1,%2,%3}, {%4,%5,%6,%7}, {%8,%9}, {%0,%1,%2,%3};"
                 : "+f"(d[0]), "+f"(d[1]), "+f"(d[2]), "+f"(d[3])
                 : "r"(a[0]), "r"(a[1]), "r"(a[2]), "r"(a[3]), "r"(b0), "r"(b1));
}

__device__ __forceinline__ void cp_B(uint32_t base, int s, int k0, int tid) {
    uint32_t dst = base + OFF_B(s);
    const char* src = (const char*)g_W1bf + (size_t)k0 * 2;
    #pragma unroll
    for (int i = 0; i < 8; i++) {
        int c  = tid + 256 * i;
        int n  = c >> 3, kc = c & 7;
        uint32_t d = dst + (unsigned)n * LDA + (unsigned)kc * 16;
        const void* g = src + (size_t)n * (DIMIN * 2) + kc * 16;
        asm volatile("cp.async.cg.shared.global [%0], [%1], 16;" :: "r"(d), "l"(g));
    }
}

__device__ __forceinline__ void ldgA(float4* areg, const float* x,
                                     int row0, int it, int tid, int h) {
    const int r0 = h * 64 + (tid >> 4), fc = tid & 15;
    const float* p = x + (size_t)(row0 + r0) * DIMIN + it * BK + fc * 4;
    #pragma unroll
    for (int i = 0; i < 4; i++)
        areg[i] = *(const float4*)(p + (size_t)(16 * i) * DIMIN);
}

__device__ __forceinline__ void stsA(uint32_t sA, const float4* areg, int tid, int h) {
    const int r0 = h * 64 + (tid >> 4), fc = tid & 15;
    #pragma unroll
    for (int i = 0; i < 4; i++) {
        __nv_bfloat162 lo = __floats2bfloat162_rn(areg[i].x, areg[i].y);
        __nv_bfloat162 hi = __floats2bfloat162_rn(areg[i].z, areg[i].w);
        uint32_t u0 = *(uint32_t*)&lo, u1 = *(uint32_t*)&hi;
        uint32_t d = sA + (unsigned)(r0 + 16 * i) * LDA + (unsigned)fc * 8;
        asm volatile("st.shared.v2.b32 [%0], {%1,%2};" :: "r"(d), "r"(u0), "r"(u1));
    }
}

// ---------------------------------------------------------------------------
// K0: W1 fp32 -> bf16 + zero run-state (accumulators, tickets)
// ---------------------------------------------------------------------------
__global__ __launch_bounds__(256)
void k_w1cvt(const float* __restrict__ W1) {
    int j = blockIdx.x * 256 + threadIdx.x;
    int i = j * 4;
    float4 v = *(const float4*)(W1 + i);
    __nv_bfloat162 lo = __floats2bfloat162_rn(v.x, v.y);
    __nv_bfloat162 hi = __floats2bfloat162_rn(v.z, v.w);
    uint2 u;
    u.x = *(uint32_t*)&lo;
    u.y = *(uint32_t*)&hi;
    *(uint2*)&g_W1bf[i] = u;
    if (j < NCLUS * DIMH) g_segi[j] = 0ull;
    if (j < NCLUS)        g_cnti[j] = 0u;
    if (j < NSPLIT)       g_tick[j] = 0u;
}

// ---------------------------------------------------------------------------
// K1: bf16 mma GEMM, grid 580: blocks [0,444) full tiles, [444,580) K-halves
// ---------------------------------------------------------------------------
__global__ __launch_bounds__(256, 1)
void k_gemm_seg(const float* __restrict__ x, const int* __restrict__ cid,
                const float* __restrict__ b1)
{
    extern __shared__ char sm[];
    const uint32_t base = smem_u32(sm);
    float* b1s   = (float*)(sm + OFF_B1);
    int*   cid_s = (int*)  (sm + OFF_CID);
    int*   cnt_s = (int*)  (sm + OFF_CNT);
    int*   flg_s = (int*)  (sm + OFF_FLG);

    const int tid  = threadIdx.x;
    const int lane = tid & 31, warp = tid >> 5;
    const int wn = warp & 3, wm = warp >> 2;

    // tile mapping
    int tile, it0, itN, halfidx = 0;
    const bool split = (blockIdx.x >= FULLT);
    if (!split) { tile = blockIdx.x; it0 = 0; itN = NITER; }
    else {
        int j = blockIdx.x - FULLT;
        tile = FULLT + (j >> 1);
        halfidx = j & 1;
        it0 = halfidx * (NITER / 2);
        itN = it0 + NITER / 2;
    }
    const int row0 = tile * BM;

    if (tid < 8)   cnt_s[tid] = 0;
    b1s[tid] = b1[tid];
    if (tid < 128) cid_s[tid] = cid[row0 + tid];

    float acc[4][8][4];
    #pragma unroll
    for (int mt = 0; mt < 4; mt++)
        #pragma unroll
        for (int nt = 0; nt < 8; nt++)
            #pragma unroll
            for (int q = 0; q < 4; q++) acc[mt][nt][q] = 0.0f;

    float4 areg[4];
    cp_B(base, 0, it0 * BK, tid);
    asm volatile("cp.async.commit_group;" ::: "memory");
    ldgA(areg, x, row0, it0, tid, 0);
    stsA(base + OFF_A(0), areg, tid, 0);
    ldgA(areg, x, row0, it0, tid, 1);
    stsA(base + OFF_A(0), areg, tid, 1);
    asm volatile("cp.async.wait_group 0;" ::: "memory");
    __syncthreads();

    for (int it = it0; it < itN; it++) {
        const int s = (it - it0) & 1;
        const bool nxt = (it + 1 < itN);
        if (nxt) {
            cp_B(base, s ^ 1, (it + 1) * BK, tid);
            asm volatile("cp.async.commit_group;" ::: "memory");
            ldgA(areg, x, row0, it + 1, tid, 0);
        }
        const uint32_t sA = base + OFF_A(s), sB = base + OFF_B(s);

        #pragma unroll
        for (int half = 0; half < 2; half++) {
            #pragma unroll
            for (int kq = 0; kq < 2; kq++) {
                const int ks = half * 2 + kq;
                uint32_t a[4][4];
                const uint32_t abase = sA + (unsigned)(wm * 64 + (lane & 15)) * LDA
                                     + (unsigned)ks * 32 + (unsigned)(lane >> 4) * 16;
                #pragma unroll
                for (int mt = 0; mt < 4; mt++)
                    ldm4(a[mt], abase + (unsigned)(mt * 16) * LDA);
                #pragma unroll
                for (int j = 0; j < 4; j++) {
                    uint32_t b[4];
                    ldm4(b, sB + (unsigned)(wn * 64 + j * 16 + (lane & 15)) * LDA
                              + (unsigned)ks * 32 + (unsigned)(lane >> 4) * 16);
                    #pragma unroll
                    for (int mt = 0; mt < 4; mt++) {
                        mma_bf16(acc[mt][2 * j],     a[mt], b[0], b[2]);
                        mma_bf16(acc[mt][2 * j + 1], a[mt], b[1], b[3]);
                    }
                }
            }
            if (nxt) {
                stsA(base + OFF_A(s ^ 1), areg, tid, half);
                if (half == 0) ldgA(areg, x, row0, it + 1, tid, 1);
                else asm volatile("cp.async.wait_group 0;" ::: "memory");
            }
        }
        __syncthreads();
    }

    // split-K combine: store own half; ticket 0 exits, ticket 1 merges
    if (split) {
        const int ts = tile - FULLT;
        float* myb = g_comb + (size_t)ts * 65536 + (size_t)halfidx * 32768;
        #pragma unroll
        for (int mt = 0; mt < 4; mt++)
            #pragma unroll
            for (int nt = 0; nt < 8; nt++)
                #pragma unroll
                for (int q = 0; q < 4; q++) {
                    int qi = (mt * 8 + nt) * 4 + q;
                    myb[qi * 256 + tid] = acc[mt][nt][q];
                }
        __threadfence();
        __syncthreads();
        if (tid == 0) flg_s[0] = (int)atomicAdd(&g_tick[ts], 1u);
        __syncthreads();
        if (flg_s[0] == 0) return;           // first finisher: partial stored
        __threadfence();
        const float* ob = g_comb + (size_t)ts * 65536 + (size_t)(1 - halfidx) * 32768;
        #pragma unroll
        for (int mt = 0; mt < 4; mt++)
            #pragma unroll
            for (int nt = 0; nt < 8; nt++)
                #pragma unroll
                for (int q = 0; q < 4; q++) {
                    int qi = (mt * 8 + nt) * 4 + q;
                    acc[mt][nt][q] += ob[qi * 256 + tid];
                }
    }

    // epilogue: acc -> smem hbuf
    float* hbuf = (float*)sm;
    #pragma unroll
    for (int mt = 0; mt < 4; mt++)
        #pragma unroll
        for (int nt = 0; nt < 8; nt++) {
            int gm = wm * 64 + mt * 16 + (lane >> 2);
            int gn = wn * 64 + nt * 8 + 2 * (lane & 3);
            hbuf[gm * HLD + gn]           = acc[mt][nt][0];
            hbuf[gm * HLD + gn + 1]       = acc[mt][nt][1];
            hbuf[(gm + 8) * HLD + gn]     = acc[mt][nt][2];
            hbuf[(gm + 8) * HLD + gn + 1] = acc[mt][nt][3];
        }

    if (tid < 128) {
        int cidv = cid_s[tid];
        #pragma unroll
        for (int c = 0; c < 8; c++) {
            unsigned m = __ballot_sync(0xffffffffu, cidv == c);
            if (lane == c) atomicAdd(&cnt_s[c], __popc(m));
        }
    }
    __syncthreads();

    const float bt = b1s[tid];
    float sacc[NCLUS];
    #pragma unroll
    for (int c = 0; c < NCLUS; c++) sacc[c] = 0.0f;
    #pragma unroll 4
    for (int r = 0; r < 128; r++) {
        float v = fmaxf(hbuf[r * HLD + tid] + bt, 0.0f);
        int cd = cid_s[r];
        #pragma unroll
        for (int c = 0; c < NCLUS; c++) sacc[c] += (cd == c) ? v : 0.0f;
    }
    #pragma unroll
    for (int c = 0; c < NCLUS; c++) {
        unsigned long long q = (unsigned long long)llrint((double)sacc[c] * SEG_SCALE);
        atomicAdd(&g_segi[c * DIMH + tid], q);
    }
    if (tid < 8) atomicAdd(&g_cnti[tid], (unsigned)cnt_s[tid]);
}

// ---------------------------------------------------------------------------
// K2: fused tail -- grid 128 x 256 (8 clusters x 16 row-groups)
// ---------------------------------------------------------------------------
__device__ __forceinline__ void grid_bar(int p) {
    __syncthreads();
    if (threadIdx.x == 0) {
        __threadfence();
        atomicAdd(&g_barc[p], 1u);
        while (atomicAdd(&g_barc[p], 0u) < (unsigned)TGRID) __nanosleep(64);
        __threadfence();
    }
    __syncthreads();
}

__global__ __launch_bounds__(256)
void k_tail(const float* __restrict__ Wf, const float* __restrict__ bfv,
            const float* __restrict__ Wa, const float* __restrict__ ba,
            const float* __restrict__ Wb, const float* __restrict__ bb,
            const float* __restrict__ Wc, const float* __restrict__ bc,
            float* __restrict__ out)
{
    const int b = blockIdx.x, tid = threadIdx.x;
    const int c = b >> 4, og = b & 15;
    __shared__ float hc_s[DIMH];
    __shared__ float hp_s[DIMH];
    __shared__ float rowred[16];
    __shared__ float partsm[128];
    __shared__ float logits[8];

    {
        float denom = fmaxf((float)g_cnti[c], 1.0f);
        float segv = (float)((double)g_segi[c * DIMH + tid] * (1.0 / SEG_SCALE));
        hc_s[tid] = segv * (1.0f / denom);
        __syncthreads();

        const int row = og * 16 + (tid >> 4);
        const int k0  = (tid & 15) * 16;
        const float4* w = (const float4*)(Wf + (size_t)row * DIMH + k0);
        float a = 0.0f;
        #pragma unroll
        for (int k = 0; k < 4; k++) {
            float4 wv = w[k];
            a += wv.x * hc_s[k0 + 4 * k]     + wv.y * hc_s[k0 + 4 * k + 1]
               + wv.z * hc_s[k0 + 4 * k + 2] + wv.w * hc_s[k0 + 4 * k + 3];
        }
        #pragma unroll
        for (int o = 8; o > 0; o >>= 1)
            a += __shfl_xor_sync(0xffffffffu, a, o);
        if ((tid & 15) == 0)
            g_hp[c * DIMH + row] = fmaxf(a + bfv[row], 0.0f);
    }
    grid_bar(0);

    {
        hp_s[tid] = g_hp[c * DIMH + tid];
        __syncthreads();

        const int row = og * 16 + (tid >> 4);
        const int k0  = (tid & 15) * 16;
        const float4* wa = (const float4*)(Wa + (size_t)row * DIMH + k0);
        const float4* wb = (const float4*)(Wb + (size_t)row * DIMH + k0);
        float aa = 0.0f, gg = 0.0f;
        #pragma unroll
        for (int k = 0; k < 4; k++) {
            float4 av = wa[k], bv = wb[k];
            float h0 = hp_s[k0 + 4 * k], h1 = hp_s[k0 + 4 * k + 1];
            float h2 = hp_s[k0 + 4 * k + 2], h3 = hp_s[k0 + 4 * k + 3];
            aa += av.x * h0 + av.y * h1 + av.z * h2 + av.w * h3;
            gg += bv.x * h0 + bv.y * h1 + bv.z * h2 + bv.w * h3;
        }
        #pragma unroll
        for (int o = 8; o > 0; o >>= 1) {
            aa += __shfl_xor_sync(0xffffffffu, aa, o);
            gg += __shfl_xor_sync(0xffffffffu, gg, o);
        }
        if ((tid & 15) == 0) {
            int row_l = tid >> 4;
            float a2 = aa + ba[row], g2 = gg + bb[row];
            rowred[row_l] = tanhf(a2) * (1.0f / (1.0f + expf(-g2))) * Wc[row];
        }
        __syncthreads();
        if (tid == 0) {
            float t = 0.0f;
            #pragma unroll
            for (int r = 0; r < 16; r++) t += rowred[r];
            g_part[c * 16 + og] = t;
        }
    }
    grid_bar(1);

    if (b == 0) {
        if (tid < 128) partsm[tid] = g_part[tid];
        __syncthreads();
        if (tid < 8) {
            float t = bc[0];
            #pragma unroll
            for (int k = 0; k < 16; k++) t += partsm[tid * 16 + k];
            logits[tid] = t;
        }
        __syncthreads();
        float l[NCLUS], m = -1e30f;
        #pragma unroll
        for (int cc = 0; cc < NCLUS; cc++) { l[cc] = logits[cc]; m = fmaxf(m, l[cc]); }
        float S = 0.0f;
        #pragma unroll
        for (int cc = 0; cc < NCLUS; cc++) { l[cc] = expf(l[cc] - m); S += l[cc]; }
        float o = 0.0f;
        #pragma unroll
        for (int cc = 0; cc < NCLUS; cc++) o += l[cc] * g_hp[cc * DIMH + tid];
        out[tid] = o / S;
        __syncthreads();
        if (tid == 0) {
            while (atomicAdd(&g_donec, 0u) < (unsigned)(TGRID - 1)) __nanosleep(64);
            g_barc[0] = 0; g_barc[1] = 0; g_donec = 0;
            __threadfence();
        }
    } else {
        if (tid == 0) { __threadfence(); atomicAdd(&g_donec, 1u); }
    }
}

// ---------------------------------------------------------------------------
extern "C" void kernel_launch(void* const* d_in, const int* in_sizes, int n_in,
                              void* d_out, int out_size)
{
    const float* x   = (const float*)d_in[0];
    const int*   cid = (const int*)  d_in[1];
    const float* W1  = (const float*)d_in[2];
    const float* b1  = (const float*)d_in[3];
    const float* Wf  = (const float*)d_in[4];
    const float* bf  = (const float*)d_in[5];
    const float* Wa  = (const float*)d_in[6];
    const float* ba  = (const float*)d_in[7];
    const float* Wb  = (const float*)d_in[8];
    const float* bb  = (const float*)d_in[9];
    const float* Wc  = (const float*)d_in[10];
    const float* bc  = (const float*)d_in[11];

    cudaFuncSetAttribute(k_gemm_seg, cudaFuncAttributeMaxDynamicSharedMemorySize, SMEM_DYN);

    k_w1cvt<<<256, 256>>>(W1);
    k_gemm_seg<<<NGRID, 256, SMEM_DYN>>>(x, cid, b1);
    k_tail<<<TGRID, 256>>>(Wf, bf, Wa, ba, Wb, bb, Wc, bc, (float*)d_out);
}